// round 16
// baseline (speedup 1.0000x reference)
#include <cuda_runtime.h>
#include <cuda_bf16.h>
#include <cstdint>

#define N_NODES 50000
#define N_PAD   50048   // 782 * 64
#define N_EDGES 600000
#define N_GRAPHS 64
#define CSR_BLOCKS 148
#define GEMM_BLOCKS 296
#define GEMM_TILES 782
#define FULLMASK 0xFFFFFFFFu

// ---------------- scratch: referenced DIRECTLY in device code ----------------
// INVARIANT: g_counts, g_cursor, g_pool_done are ZERO at entry of kernel_launch
// (zero-initialized at load; counts/cursor re-zeroed in k_gather64, pool_done in k_pool_fc).
__device__ int   g_is64;
__device__ float g_deg[N_NODES];                  // dinv
__device__ int   g_counts[N_NODES];
__device__ int   g_cursor[N_NODES];
__device__ int   g_rowptr[N_NODES + 1];
__device__ int   g_bsums[256];
__device__ int   g_bsum_pre[256];
__device__ int   g_pool_done;
__device__ int   g_bar_count;
__device__ volatile int g_bar_gen;
__device__ int   g_esrc[N_EDGES];
__device__ float g_enorm[N_EDGES];
__device__ __align__(16) float g_bufA[(size_t)N_NODES * 128];  // GEMM out t
__device__ __align__(16) float g_bufB[(size_t)N_NODES * 128];  // layer-3 agg out
__device__ float g_pooled[N_GRAPHS * 64];
// bf16 split operands; padding rows [50000,50048) are never written -> stay zero
__device__ __align__(16) __nv_bfloat16 g_ahi[(size_t)N_PAD * 128];
__device__ __align__(16) __nv_bfloat16 g_alo[(size_t)N_PAD * 128];
// all three transposed weights: W1T @0, W2T @16384, W3T @32768 (elements)
__device__ __align__(16) __nv_bfloat16 g_whi[40960];
__device__ __align__(16) __nv_bfloat16 g_wlo[40960];

// ---------------- helpers ----------------
__device__ __forceinline__ uint32_t smem_u32(const void* p) {
    uint32_t a;
    asm("{ .reg .u64 t; cvta.to.shared.u64 t, %1; cvt.u32.u64 %0, t; }" : "=r"(a) : "l"(p));
    return a;
}
__device__ __forceinline__ void ldsm_x4(uint32_t* r, uint32_t addr) {
    asm volatile("ldmatrix.sync.aligned.m8n8.x4.shared.b16 {%0,%1,%2,%3}, [%4];"
                 : "=r"(r[0]), "=r"(r[1]), "=r"(r[2]), "=r"(r[3]) : "r"(addr));
}
__device__ __forceinline__ void mma_bf16(float* d, const uint32_t* a, uint32_t b0, uint32_t b1) {
    asm volatile(
        "mma.sync.aligned.m16n8k16.row.col.f32.bf16.bf16.f32 "
        "{%0,%1,%2,%3}, {%4,%5,%6,%7}, {%8,%9}, {%0,%1,%2,%3};"
        : "+f"(d[0]), "+f"(d[1]), "+f"(d[2]), "+f"(d[3])
        : "r"(a[0]), "r"(a[1]), "r"(a[2]), "r"(a[3]), "r"(b0), "r"(b1));
}
__device__ __forceinline__ void cp16(uint32_t saddr, const void* gptr) {
    asm volatile("cp.async.cg.shared.global [%0], [%1], 16;" :: "r"(saddr), "l"(gptr));
}
__device__ __forceinline__ void cp_wait_all() {
    asm volatile("cp.async.commit_group;");
    asm volatile("cp.async.wait_group 0;" ::: "memory");
}
__device__ __forceinline__ int load_idx2(const void* p, long long i, int is64) {
    if (is64) return (int)((const long long*)p)[i];
    return ((const int*)p)[i];
}
__device__ __forceinline__ void split2(float a, float b, uint32_t& hi, uint32_t& lo) {
    __nv_bfloat16 h0 = __float2bfloat16_rn(a), h1 = __float2bfloat16_rn(b);
    __nv_bfloat16 l0 = __float2bfloat16_rn(a - __bfloat162float(h0));
    __nv_bfloat16 l1 = __float2bfloat16_rn(b - __bfloat162float(h1));
    __nv_bfloat162 hp(h0, h1), lp(l0, l1);
    hi = *(uint32_t*)&hp;
    lo = *(uint32_t*)&lp;
}
// grid barrier: all CSR_BLOCKS blocks are co-resident (csr blocks use 0 smem, ~16 regs;
// even sharing SMs with the concurrent GEMM they fit; worst case GEMM drains first)
__device__ __forceinline__ void grid_bar() {
    __syncthreads();
    if (threadIdx.x == 0) {
        __threadfence();
        int gen = g_bar_gen;
        if (atomicAdd(&g_bar_count, 1) == CSR_BLOCKS - 1) {
            g_bar_count = 0;
            __threadfence();
            g_bar_gen = gen + 1;
        } else {
            while (g_bar_gen == gen) { }
        }
    }
    __syncthreads();
}
__device__ __forceinline__ int block_scan256(int v, int* wsum) {
    int lane = threadIdx.x & 31, wid = threadIdx.x >> 5;
    int s = v;
#pragma unroll
    for (int o = 1; o < 32; o <<= 1) {
        int t = __shfl_up_sync(FULLMASK, s, o);
        if (lane >= o) s += t;
    }
    if (lane == 31) wsum[wid] = s;
    __syncthreads();
    if (wid == 0) {
        int t = (lane < 8) ? wsum[lane] : 0;
        int t2 = t;
#pragma unroll
        for (int o = 1; o < 8; o <<= 1) {
            int u = __shfl_up_sync(FULLMASK, t2, o);
            if (lane >= o) t2 += u;
        }
        if (lane < 8) wsum[lane] = t2 - t;
    }
    __syncthreads();
    return s + wsum[wid];
}

// ---------------- W splits (runs on side stream, parallel with k_csr) ----------------
__global__ void k_splitW(const float* __restrict__ W1, const float* __restrict__ W2,
                         const float* __restrict__ W3) {
    int i = blockIdx.x * blockDim.x + threadIdx.x;
    if (i >= 40960) return;
    const float* W;
    int Ncols, local;
    if (i < 16384)      { W = W1; Ncols = 128; local = i; }
    else if (i < 32768) { W = W2; Ncols = 128; local = i - 16384; }
    else                { W = W3; Ncols = 64;  local = i - 32768; }
    int k = local & 127, n = local >> 7;
    float w = W[(size_t)k * Ncols + n];
    __nv_bfloat16 h = __float2bfloat16_rn(w);
    g_whi[i] = h;
    g_wlo[i] = __float2bfloat16_rn(w - __bfloat162float(h));
}

// ================= fused CSR build (histogram/scan/bucket only) =================
__global__ void __launch_bounds__(256) k_csr(const void* __restrict__ ei) {
    int tid = threadIdx.x, bid = blockIdx.x;
    int gidx = bid * 256 + tid;
    const int gstr = CSR_BLOCKS * 256;
    const int* e32 = (const int*)ei;
    int is64 = ((e32[1] | e32[3] | e32[5] | e32[7] | e32[9] | e32[11]) == 0);
    if (gidx == 0) g_is64 = is64;
    __shared__ int wsum[8];

    for (int i = gidx; i < N_EDGES; i += gstr) {
        int c = load_idx2(ei, (long long)N_EDGES + i, is64);
        if ((unsigned)c < N_NODES) atomicAdd(&g_counts[c], 1);
    }
    grid_bar();

    for (int c = bid; c < 196; c += CSR_BLOCKS) {
        int i = c * 256 + tid;
        int v = (i < N_NODES) ? g_counts[i] : 0;
        int incl = block_scan256(v, wsum);
        if (i < N_NODES) g_rowptr[i] = incl - v;
        if (tid == 255) g_bsums[c] = incl;
        __syncthreads();
    }
    grid_bar();

    if (bid == 0) {
        int v = (tid < 196) ? g_bsums[tid] : 0;
        int incl = block_scan256(v, wsum);
        g_bsum_pre[tid] = incl - v;
        if (tid == 255) g_rowptr[N_NODES] = incl;
    }
    grid_bar();

    for (int i = gidx; i < N_NODES; i += gstr) {
        g_rowptr[i] += g_bsum_pre[i >> 8];
        g_deg[i] = rsqrtf(1.0f + (float)g_counts[i]);
    }
    grid_bar();

    for (int i = gidx; i < N_EDGES; i += gstr) {
        int r = load_idx2(ei, i, is64);
        int c = load_idx2(ei, (long long)N_EDGES + i, is64);
        if ((unsigned)c < N_NODES && (unsigned)r < N_NODES) {
            int pos = g_rowptr[c] + atomicAdd(&g_cursor[c], 1);
            g_esrc[pos] = r;
            g_enorm[pos] = g_deg[r] * g_deg[c];
        }
    }
}

// ================= multi-tile persistent-B mma.sync GEMM (round-12/14 tiling) =================
template <int NC, bool F32A>
__global__ void __launch_bounds__(256, 2) k_gemm_mma(const float* __restrict__ Aext, int wofs) {
    extern __shared__ __align__(16) char smem[];
    const int A_HI = 0, A_LO = 16384, B_HI = 32768, B_LO = 32768 + NC * 256;
    int tid = threadIdx.x;
    int wid = tid >> 5, lane = tid & 31;
    uint32_t sb = smem_u32(smem);

    // ---- B tiles: once per block (cp.async) ----
    const char* wh = reinterpret_cast<const char*>(g_whi + wofs);
    const char* wl = reinterpret_cast<const char*>(g_wlo + wofs);
    for (int c = tid; c < NC * 16; c += 256) {
        int n = c >> 4, kc = c & 15;
        size_t gof = (size_t)n * 256 + kc * 16;
        int off = n * 256 + ((kc ^ (n & 7)) * 16);
        cp16(sb + B_HI + off, wh + gof);
        cp16(sb + B_LO + off, wl + gof);
    }

    const int NT = NC / 16;
    const int NP = NC / 32;
    int wm = (wid & 3) * 16;
    int wn = (wid >> 2) * (NC / 2);
    int gid = lane >> 2, tig = lane & 3;

    for (int tile = blockIdx.x; tile < GEMM_TILES; tile += GEMM_BLOCKS) {
        int row0 = tile * 64;
        if (F32A) {
            for (int c = tid; c < 64 * 32; c += 256) {
                int m = c >> 5, q = c & 31;
                float4 v = make_float4(0.f, 0.f, 0.f, 0.f);
                if (row0 + m < N_NODES)
                    v = *reinterpret_cast<const float4*>(Aext + (size_t)(row0 + m) * 128 + q * 4);
                uint2 hv, lv;
                split2(v.x, v.y, hv.x, lv.x);
                split2(v.z, v.w, hv.y, lv.y);
                int kc = q >> 1;
                int off = m * 256 + ((kc ^ (m & 7)) * 16) + (q & 1) * 8;
                *reinterpret_cast<uint2*>(smem + A_HI + off) = hv;
                *reinterpret_cast<uint2*>(smem + A_LO + off) = lv;
            }
            cp_wait_all();  // B (first iter); no-op later
        } else {
            for (int c = tid; c < 64 * 16; c += 256) {
                int m = c >> 4, kc = c & 15;
                size_t gof = ((size_t)(row0 + m)) * 256 + kc * 16;
                int off = m * 256 + ((kc ^ (m & 7)) * 16);
                cp16(sb + A_HI + off, reinterpret_cast<const char*>(g_ahi) + gof);
                cp16(sb + A_LO + off, reinterpret_cast<const char*>(g_alo) + gof);
            }
            cp_wait_all();
        }
        __syncthreads();

        float acc[NT][4];
#pragma unroll
        for (int nt = 0; nt < NT; nt++)
#pragma unroll
            for (int j = 0; j < 4; j++) acc[nt][j] = 0.0f;

#pragma unroll
        for (int ks = 0; ks < 8; ks++) {
            uint32_t ah[4], al[4];
            {
                int r = wm + (lane & 15);
                int ch = ks * 2 + (lane >> 4);
                int off = r * 256 + ((ch ^ (r & 7)) * 16);
                ldsm_x4(ah, sb + A_HI + off);
                ldsm_x4(al, sb + A_LO + off);
            }
            uint32_t bh[NP][4], bl[NP][4];
#pragma unroll
            for (int p = 0; p < NP; p++) {
                int n = wn + p * 16 + (lane & 7) + ((lane >> 4) << 3);
                int ch = ks * 2 + ((lane >> 3) & 1);
                int off = n * 256 + ((ch ^ (n & 7)) * 16);
                ldsm_x4(bh[p], sb + B_HI + off);
                ldsm_x4(bl[p], sb + B_LO + off);
            }
#pragma unroll
            for (int nt = 0; nt < NT; nt++) {
                uint32_t h0 = bh[nt >> 1][(nt & 1) * 2], h1 = bh[nt >> 1][(nt & 1) * 2 + 1];
                uint32_t l0 = bl[nt >> 1][(nt & 1) * 2], l1 = bl[nt >> 1][(nt & 1) * 2 + 1];
                mma_bf16(acc[nt], ah, h0, h1);
                mma_bf16(acc[nt], ah, l0, l1);
                mma_bf16(acc[nt], al, h0, h1);
            }
        }

#pragma unroll
        for (int nt = 0; nt < NT; nt++) {
            int col = wn + nt * 8 + tig * 2;
            int m0 = row0 + wm + gid;
            if (m0 < N_NODES)
                *reinterpret_cast<float2*>(g_bufA + (size_t)m0 * NC + col) =
                    make_float2(acc[nt][0], acc[nt][1]);
            if (m0 + 8 < N_NODES)
                *reinterpret_cast<float2*>(g_bufA + (size_t)(m0 + 8) * NC + col) =
                    make_float2(acc[nt][2], acc[nt][3]);
        }
        __syncthreads();  // all warps done reading A before next tile overwrites
    }
}

// ---------------- CSR gather, shuffle-batched edges ----------------
__global__ void k_gather128_split(const float* __restrict__ b) {
    int node = (blockIdx.x * blockDim.x + threadIdx.x) >> 5;
    int lane = threadIdx.x & 31;
    if (node >= N_NODES) return;
    const float* t = g_bufA;
    float d = g_deg[node];
    float d2 = d * d;
    float4 self = *reinterpret_cast<const float4*>(t + (size_t)node * 128 + lane * 4);
    float4 bv = *reinterpret_cast<const float4*>(b + lane * 4);
    float4 acc;
    acc.x = fmaf(d2, self.x, bv.x);
    acc.y = fmaf(d2, self.y, bv.y);
    acc.z = fmaf(d2, self.z, bv.z);
    acc.w = fmaf(d2, self.w, bv.w);

    int s = g_rowptr[node], e = g_rowptr[node + 1];
    for (int base = s; base < e; base += 32) {
        int cnt = min(32, e - base);
        int rs = 0; float wn = 0.0f;
        if (base + lane < e) { rs = g_esrc[base + lane]; wn = g_enorm[base + lane]; }
        int j = 0;
        for (; j + 4 <= cnt; j += 4) {
            int r0 = __shfl_sync(FULLMASK, rs, j + 0);
            int r1 = __shfl_sync(FULLMASK, rs, j + 1);
            int r2 = __shfl_sync(FULLMASK, rs, j + 2);
            int r3 = __shfl_sync(FULLMASK, rs, j + 3);
            float w0 = __shfl_sync(FULLMASK, wn, j + 0);
            float w1 = __shfl_sync(FULLMASK, wn, j + 1);
            float w2 = __shfl_sync(FULLMASK, wn, j + 2);
            float w3 = __shfl_sync(FULLMASK, wn, j + 3);
            float4 v0 = *reinterpret_cast<const float4*>(t + (size_t)r0 * 128 + lane * 4);
            float4 v1 = *reinterpret_cast<const float4*>(t + (size_t)r1 * 128 + lane * 4);
            float4 v2 = *reinterpret_cast<const float4*>(t + (size_t)r2 * 128 + lane * 4);
            float4 v3 = *reinterpret_cast<const float4*>(t + (size_t)r3 * 128 + lane * 4);
            acc.x = fmaf(w0, v0.x, acc.x); acc.y = fmaf(w0, v0.y, acc.y);
            acc.z = fmaf(w0, v0.z, acc.z); acc.w = fmaf(w0, v0.w, acc.w);
            acc.x = fmaf(w1, v1.x, acc.x); acc.y = fmaf(w1, v1.y, acc.y);
            acc.z = fmaf(w1, v1.z, acc.z); acc.w = fmaf(w1, v1.w, acc.w);
            acc.x = fmaf(w2, v2.x, acc.x); acc.y = fmaf(w2, v2.y, acc.y);
            acc.z = fmaf(w2, v2.z, acc.z); acc.w = fmaf(w2, v2.w, acc.w);
            acc.x = fmaf(w3, v3.x, acc.x); acc.y = fmaf(w3, v3.y, acc.y);
            acc.z = fmaf(w3, v3.z, acc.z); acc.w = fmaf(w3, v3.w, acc.w);
        }
        for (; j < cnt; j++) {
            int r0 = __shfl_sync(FULLMASK, rs, j);
            float w0 = __shfl_sync(FULLMASK, wn, j);
            float4 v0 = *reinterpret_cast<const float4*>(t + (size_t)r0 * 128 + lane * 4);
            acc.x = fmaf(w0, v0.x, acc.x); acc.y = fmaf(w0, v0.y, acc.y);
            acc.z = fmaf(w0, v0.z, acc.z); acc.w = fmaf(w0, v0.w, acc.w);
        }
    }
    acc.x = fmaxf(acc.x, 0.0f); acc.y = fmaxf(acc.y, 0.0f);
    acc.z = fmaxf(acc.z, 0.0f); acc.w = fmaxf(acc.w, 0.0f);
    uint2 hv, lv;
    split2(acc.x, acc.y, hv.x, lv.x);
    split2(acc.z, acc.w, hv.y, lv.y);
    reinterpret_cast<uint2*>(g_ahi)[node * 32 + lane] = hv;
    reinterpret_cast<uint2*>(g_alo)[node * 32 + lane] = lv;
}

// layer-3 gather; also restores the counts/cursor zero-invariant
__global__ void k_gather64(const float* __restrict__ b) {
    int gthread = blockIdx.x * blockDim.x + threadIdx.x;
    if (gthread < N_NODES) { g_counts[gthread] = 0; g_cursor[gthread] = 0; }
    int node = gthread >> 5;
    int lane = threadIdx.x & 31;
    if (node >= N_NODES) return;
    const float* t = g_bufA;
    float d = g_deg[node];
    float d2 = d * d;
    float2 self = *reinterpret_cast<const float2*>(t + (size_t)node * 64 + lane * 2);
    float2 bv = *reinterpret_cast<const float2*>(b + lane * 2);
    float2 acc;
    acc.x = fmaf(d2, self.x, bv.x);
    acc.y = fmaf(d2, self.y, bv.y);

    int s = g_rowptr[node], e = g_rowptr[node + 1];
    for (int base = s; base < e; base += 32) {
        int cnt = min(32, e - base);
        int rs = 0; float wn = 0.0f;
        if (base + lane < e) { rs = g_esrc[base + lane]; wn = g_enorm[base + lane]; }
        int j = 0;
        for (; j + 4 <= cnt; j += 4) {
            int r0 = __shfl_sync(FULLMASK, rs, j + 0);
            int r1 = __shfl_sync(FULLMASK, rs, j + 1);
            int r2 = __shfl_sync(FULLMASK, rs, j + 2);
            int r3 = __shfl_sync(FULLMASK, rs, j + 3);
            float w0 = __shfl_sync(FULLMASK, wn, j + 0);
            float w1 = __shfl_sync(FULLMASK, wn, j + 1);
            float w2 = __shfl_sync(FULLMASK, wn, j + 2);
            float w3 = __shfl_sync(FULLMASK, wn, j + 3);
            float2 v0 = *reinterpret_cast<const float2*>(t + (size_t)r0 * 64 + lane * 2);
            float2 v1 = *reinterpret_cast<const float2*>(t + (size_t)r1 * 64 + lane * 2);
            float2 v2 = *reinterpret_cast<const float2*>(t + (size_t)r2 * 64 + lane * 2);
            float2 v3 = *reinterpret_cast<const float2*>(t + (size_t)r3 * 64 + lane * 2);
            acc.x = fmaf(w0, v0.x, acc.x); acc.y = fmaf(w0, v0.y, acc.y);
            acc.x = fmaf(w1, v1.x, acc.x); acc.y = fmaf(w1, v1.y, acc.y);
            acc.x = fmaf(w2, v2.x, acc.x); acc.y = fmaf(w2, v2.y, acc.y);
            acc.x = fmaf(w3, v3.x, acc.x); acc.y = fmaf(w3, v3.y, acc.y);
        }
        for (; j < cnt; j++) {
            int r0 = __shfl_sync(FULLMASK, rs, j);
            float w0 = __shfl_sync(FULLMASK, wn, j);
            float2 v0 = *reinterpret_cast<const float2*>(t + (size_t)r0 * 64 + lane * 2);
            acc.x = fmaf(w0, v0.x, acc.x); acc.y = fmaf(w0, v0.y, acc.y);
        }
    }
    *reinterpret_cast<float2*>(g_bufB + (size_t)node * 64 + lane * 2) = acc;
}

// ---------------- mean pool + FC (last-block) ----------------
__global__ void k_pool_fc(const void* __restrict__ batch,
                          const float* __restrict__ Wf1, const float* __restrict__ bf1,
                          const float* __restrict__ Wf2, const float* __restrict__ bf2,
                          float* __restrict__ out) {
    int g = blockIdx.x;
    const int N = N_NODES;
    int is64 = g_is64;
    int lo = 0, hi = N;
    while (lo < hi) { int mid = (lo + hi) >> 1; if (load_idx2(batch, mid, is64) < g) lo = mid + 1; else hi = mid; }
    int start = lo;
    lo = start; hi = N;
    while (lo < hi) { int mid = (lo + hi) >> 1; if (load_idx2(batch, mid, is64) < g + 1) lo = mid + 1; else hi = mid; }
    int end = lo;

    int f = threadIdx.x & 63;
    int grp = threadIdx.x >> 6;
    __shared__ float red[4][64];

    float acc = 0.0f;
    for (int i = start + grp; i < end; i += 4)
        acc += fmaxf(g_bufB[(size_t)i * 64 + f], 0.0f);
    red[grp][f] = acc;
    __syncthreads();
    if (grp == 0) {
        float s = red[0][f] + red[1][f] + red[2][f] + red[3][f];
        float cnt = (float)(end - start);
        g_pooled[g * 64 + f] = s / fmaxf(cnt, 1.0f);
    }

    __threadfence();
    __shared__ int amLast;
    if (threadIdx.x == 0)
        amLast = (atomicAdd(&g_pool_done, 1) == (int)gridDim.x - 1);
    __syncthreads();
    if (!amLast) return;

    __shared__ float P[64 * 64];
    __shared__ float Hd[64 * 32];
    for (int i = threadIdx.x; i < 64 * 64; i += 256) P[i] = g_pooled[i];
    __syncthreads();
    for (int e2 = threadIdx.x; e2 < 64 * 32; e2 += 256) {
        int gi = e2 >> 5, j = e2 & 31;
        float s = bf1[j];
#pragma unroll
        for (int k = 0; k < 64; k++) s += P[gi * 64 + k] * Wf1[k * 32 + j];
        Hd[e2] = fmaxf(s, 0.0f);
    }
    __syncthreads();
    for (int e2 = threadIdx.x; e2 < 64 * 10; e2 += 256) {
        int gi = e2 / 10, j = e2 % 10;
        float s = bf2[j];
#pragma unroll
        for (int k = 0; k < 32; k++) s += Hd[gi * 32 + k] * Wf2[k * 10 + j];
        out[e2] = s;
    }
    if (threadIdx.x == 0) g_pool_done = 0;
}

// ---------------- launch ----------------
extern "C" void kernel_launch(void* const* d_in, const int* in_sizes, int n_in,
                              void* d_out, int out_size) {
    const float *x = 0, *W1 = 0, *b1 = 0, *W2 = 0, *b2 = 0, *W3 = 0, *b3 = 0;
    const float *Wf1 = 0, *bf1 = 0, *Wf2 = 0, *bf2 = 0;
    const void *ei = 0, *batch = 0;
    for (int i = 0; i < n_in; i++) {
        const void* p = d_in[i];
        switch (in_sizes[i]) {
            case 6400000: x = (const float*)p; break;
            case 1200000: ei = p; break;
            case 50000:   batch = p; break;
            case 16384:   if (!W1) W1 = (const float*)p; else W2 = (const float*)p; break;
            case 128:     if (!b1) b1 = (const float*)p; else b2 = (const float*)p; break;
            case 8192:    W3 = (const float*)p; break;
            case 64:      b3 = (const float*)p; break;
            case 2048:    Wf1 = (const float*)p; break;
            case 32:      bf1 = (const float*)p; break;
            case 320:     Wf2 = (const float*)p; break;
            case 10:      bf2 = (const float*)p; break;
        }
    }

    const int N = N_NODES;
    const int SMEM128 = 32768 + 2 * 128 * 256;  // 98304
    const int SMEM64  = 32768 + 2 * 64 * 256;   // 65536
    cudaFuncSetAttribute(k_gemm_mma<128, true>,  cudaFuncAttributeMaxDynamicSharedMemorySize, SMEM128);
    cudaFuncSetAttribute(k_gemm_mma<128, false>, cudaFuncAttributeMaxDynamicSharedMemorySize, SMEM128);
    cudaFuncSetAttribute(k_gemm_mma<64, false>,  cudaFuncAttributeMaxDynamicSharedMemorySize, SMEM64);

    // side stream + events (created once; no device allocation involved)
    static cudaStream_t s2 = nullptr;
    static cudaEvent_t evFork = nullptr, evJoin = nullptr;
    if (!s2) {
        cudaStreamCreateWithFlags(&s2, cudaStreamNonBlocking);
        cudaEventCreateWithFlags(&evFork, cudaEventDisableTiming);
        cudaEventCreateWithFlags(&evJoin, cudaEventDisableTiming);
    }

    int gath_grid = (N * 32 + 255) / 256;

    // fork: splitW + layer-1 GEMM (depend only on x, W) run concurrently with CSR build
    cudaEventRecord(evFork, 0);
    cudaStreamWaitEvent(s2, evFork, 0);
    k_splitW<<<(40960 + 255) / 256, 256, 0, s2>>>(W1, W2, W3);
    k_gemm_mma<128, true><<<GEMM_BLOCKS, 256, SMEM128, s2>>>(x, 0);

    k_csr<<<CSR_BLOCKS, 256>>>(ei);  // main stream (counts/cursor zero by invariant)

    // join: gather1 needs both CSR arrays (main stream) and bufA (s2)
    cudaEventRecord(evJoin, s2);
    cudaStreamWaitEvent(0, evJoin, 0);

    k_gather128_split<<<gath_grid, 256>>>(b1);
    // layer 2
    k_gemm_mma<128, false><<<GEMM_BLOCKS, 256, SMEM128>>>(nullptr, 16384);
    k_gather128_split<<<gath_grid, 256>>>(b2);
    // layer 3
    k_gemm_mma<64, false><<<GEMM_BLOCKS, 256, SMEM64>>>(nullptr, 32768);
    k_gather64<<<gath_grid, 256>>>(b3);

    // pool + FC fused
    k_pool_fc<<<N_GRAPHS, 256>>>(batch, Wf1, bf1, Wf2, bf2, (float*)d_out);
}

// round 17
// speedup vs baseline: 1.2445x; 1.2445x over previous
#include <cuda_runtime.h>
#include <cuda_bf16.h>
#include <cstdint>

#define N_NODES 50000
#define N_PAD   50048   // 782 * 64
#define N_EDGES 600000
#define N_GRAPHS 64
#define CSR_BLOCKS 148
#define GEMM_BLOCKS 296
#define GEMM_TILES 782
#define FULLMASK 0xFFFFFFFFu

// ---------------- scratch: referenced DIRECTLY in device code ----------------
// INVARIANT: g_counts, g_cursor, g_pool_done are ZERO at entry of kernel_launch
// (zero-initialized at load; counts/cursor re-zeroed in k_gather64, pool_done in k_pool_fc).
__device__ int   g_is64;
__device__ float g_deg[N_NODES];                  // dinv
__device__ int   g_counts[N_NODES];
__device__ int   g_cursor[N_NODES];
__device__ int   g_rowptr[N_NODES + 1];
__device__ int   g_bsums[256];
__device__ int   g_bsum_pre[256];
__device__ int   g_pool_done;
__device__ int   g_bar_count;
__device__ volatile int g_bar_gen;
__device__ __align__(8) int2 g_epack[N_EDGES];    // (src, __float_as_int(norm))
__device__ __align__(16) float g_bufA[(size_t)N_NODES * 128];  // GEMM out t
__device__ __align__(16) float g_bufB[(size_t)N_NODES * 128];  // layer-3 agg out
__device__ float g_pooled[N_GRAPHS * 64];
// bf16 split operands; padding rows [50000,50048) are never written -> stay zero
__device__ __align__(16) __nv_bfloat16 g_ahi[(size_t)N_PAD * 128];
__device__ __align__(16) __nv_bfloat16 g_alo[(size_t)N_PAD * 128];
// all three transposed weights: W1T @0, W2T @16384, W3T @32768 (elements)
__device__ __align__(16) __nv_bfloat16 g_whi[40960];
__device__ __align__(16) __nv_bfloat16 g_wlo[40960];

// ---------------- helpers ----------------
__device__ __forceinline__ uint32_t smem_u32(const void* p) {
    uint32_t a;
    asm("{ .reg .u64 t; cvta.to.shared.u64 t, %1; cvt.u32.u64 %0, t; }" : "=r"(a) : "l"(p));
    return a;
}
__device__ __forceinline__ void ldsm_x4(uint32_t* r, uint32_t addr) {
    asm volatile("ldmatrix.sync.aligned.m8n8.x4.shared.b16 {%0,%1,%2,%3}, [%4];"
                 : "=r"(r[0]), "=r"(r[1]), "=r"(r[2]), "=r"(r[3]) : "r"(addr));
}
__device__ __forceinline__ void mma_bf16(float* d, const uint32_t* a, uint32_t b0, uint32_t b1) {
    asm volatile(
        "mma.sync.aligned.m16n8k16.row.col.f32.bf16.bf16.f32 "
        "{%0,%1,%2,%3}, {%4,%5,%6,%7}, {%8,%9}, {%0,%1,%2,%3};"
        : "+f"(d[0]), "+f"(d[1]), "+f"(d[2]), "+f"(d[3])
        : "r"(a[0]), "r"(a[1]), "r"(a[2]), "r"(a[3]), "r"(b0), "r"(b1));
}
__device__ __forceinline__ void cp16(uint32_t saddr, const void* gptr) {
    asm volatile("cp.async.cg.shared.global [%0], [%1], 16;" :: "r"(saddr), "l"(gptr));
}
__device__ __forceinline__ void cp_wait_all() {
    asm volatile("cp.async.commit_group;");
    asm volatile("cp.async.wait_group 0;" ::: "memory");
}
__device__ __forceinline__ int load_idx2(const void* p, long long i, int is64) {
    if (is64) return (int)((const long long*)p)[i];
    return ((const int*)p)[i];
}
__device__ __forceinline__ void split2(float a, float b, uint32_t& hi, uint32_t& lo) {
    __nv_bfloat16 h0 = __float2bfloat16_rn(a), h1 = __float2bfloat16_rn(b);
    __nv_bfloat16 l0 = __float2bfloat16_rn(a - __bfloat162float(h0));
    __nv_bfloat16 l1 = __float2bfloat16_rn(b - __bfloat162float(h1));
    __nv_bfloat162 hp(h0, h1), lp(l0, l1);
    hi = *(uint32_t*)&hp;
    lo = *(uint32_t*)&lp;
}
// grid barrier: all CSR_BLOCKS blocks are co-resident (148 blocks on 148 SMs,
// k_csr launched alone on a single stream)
__device__ __forceinline__ void grid_bar() {
    __syncthreads();
    if (threadIdx.x == 0) {
        __threadfence();
        int gen = g_bar_gen;
        if (atomicAdd(&g_bar_count, 1) == CSR_BLOCKS - 1) {
            g_bar_count = 0;
            __threadfence();
            g_bar_gen = gen + 1;
        } else {
            while (g_bar_gen == gen) { }
        }
    }
    __syncthreads();
}
__device__ __forceinline__ int block_scan256(int v, int* wsum) {
    int lane = threadIdx.x & 31, wid = threadIdx.x >> 5;
    int s = v;
#pragma unroll
    for (int o = 1; o < 32; o <<= 1) {
        int t = __shfl_up_sync(FULLMASK, s, o);
        if (lane >= o) s += t;
    }
    if (lane == 31) wsum[wid] = s;
    __syncthreads();
    if (wid == 0) {
        int t = (lane < 8) ? wsum[lane] : 0;
        int t2 = t;
#pragma unroll
        for (int o = 1; o < 8; o <<= 1) {
            int u = __shfl_up_sync(FULLMASK, t2, o);
            if (lane >= o) t2 += u;
        }
        if (lane < 8) wsum[lane] = t2 - t;
    }
    __syncthreads();
    return s + wsum[wid];
}

// ================= fused CSR build (W splits + histogram + scan + bucket) =================
__global__ void __launch_bounds__(256) k_csr(const void* __restrict__ ei,
                                             const float* __restrict__ W1,
                                             const float* __restrict__ W2,
                                             const float* __restrict__ W3) {
    int tid = threadIdx.x, bid = blockIdx.x;
    int gidx = bid * 256 + tid;
    const int gstr = CSR_BLOCKS * 256;
    const int* e32 = (const int*)ei;
    int is64 = ((e32[1] | e32[3] | e32[5] | e32[7] | e32[9] | e32[11]) == 0);
    if (gidx == 0) g_is64 = is64;
    __shared__ int wsum[8];

    for (int i = gidx; i < 40960; i += gstr) {
        const float* W;
        int Ncols, local;
        if (i < 16384)      { W = W1; Ncols = 128; local = i; }
        else if (i < 32768) { W = W2; Ncols = 128; local = i - 16384; }
        else                { W = W3; Ncols = 64;  local = i - 32768; }
        int k = local & 127, n = local >> 7;
        float w = W[(size_t)k * Ncols + n];
        __nv_bfloat16 h = __float2bfloat16_rn(w);
        g_whi[i] = h;
        g_wlo[i] = __float2bfloat16_rn(w - __bfloat162float(h));
    }
    for (int i = gidx; i < N_EDGES; i += gstr) {
        int c = load_idx2(ei, (long long)N_EDGES + i, is64);
        if ((unsigned)c < N_NODES) atomicAdd(&g_counts[c], 1);
    }
    grid_bar();

    for (int c = bid; c < 196; c += CSR_BLOCKS) {
        int i = c * 256 + tid;
        int v = (i < N_NODES) ? g_counts[i] : 0;
        int incl = block_scan256(v, wsum);
        if (i < N_NODES) g_rowptr[i] = incl - v;
        if (tid == 255) g_bsums[c] = incl;
        __syncthreads();
    }
    grid_bar();

    if (bid == 0) {
        int v = (tid < 196) ? g_bsums[tid] : 0;
        int incl = block_scan256(v, wsum);
        g_bsum_pre[tid] = incl - v;
        if (tid == 255) g_rowptr[N_NODES] = incl;
    }
    grid_bar();

    for (int i = gidx; i < N_NODES; i += gstr) {
        g_rowptr[i] += g_bsum_pre[i >> 8];
        g_deg[i] = rsqrtf(1.0f + (float)g_counts[i]);
    }
    grid_bar();

    for (int i = gidx; i < N_EDGES; i += gstr) {
        int r = load_idx2(ei, i, is64);
        int c = load_idx2(ei, (long long)N_EDGES + i, is64);
        if ((unsigned)c < N_NODES && (unsigned)r < N_NODES) {
            int pos = g_rowptr[c] + atomicAdd(&g_cursor[c], 1);
            g_epack[pos] = make_int2(r, __float_as_int(g_deg[r] * g_deg[c]));
        }
    }
}

// ================= multi-tile persistent-B mma.sync GEMM (round-12/14 tiling) =================
template <int NC, bool F32A>
__global__ void __launch_bounds__(256, 2) k_gemm_mma(const float* __restrict__ Aext, int wofs) {
    extern __shared__ __align__(16) char smem[];
    const int A_HI = 0, A_LO = 16384, B_HI = 32768, B_LO = 32768 + NC * 256;
    int tid = threadIdx.x;
    int wid = tid >> 5, lane = tid & 31;
    uint32_t sb = smem_u32(smem);

    // ---- B tiles: once per block (cp.async) ----
    const char* wh = reinterpret_cast<const char*>(g_whi + wofs);
    const char* wl = reinterpret_cast<const char*>(g_wlo + wofs);
    for (int c = tid; c < NC * 16; c += 256) {
        int n = c >> 4, kc = c & 15;
        size_t gof = (size_t)n * 256 + kc * 16;
        int off = n * 256 + ((kc ^ (n & 7)) * 16);
        cp16(sb + B_HI + off, wh + gof);
        cp16(sb + B_LO + off, wl + gof);
    }

    const int NT = NC / 16;
    const int NP = NC / 32;
    int wm = (wid & 3) * 16;
    int wn = (wid >> 2) * (NC / 2);
    int gid = lane >> 2, tig = lane & 3;

    for (int tile = blockIdx.x; tile < GEMM_TILES; tile += GEMM_BLOCKS) {
        int row0 = tile * 64;
        if (F32A) {
            for (int c = tid; c < 64 * 32; c += 256) {
                int m = c >> 5, q = c & 31;
                float4 v = make_float4(0.f, 0.f, 0.f, 0.f);
                if (row0 + m < N_NODES)
                    v = *reinterpret_cast<const float4*>(Aext + (size_t)(row0 + m) * 128 + q * 4);
                uint2 hv, lv;
                split2(v.x, v.y, hv.x, lv.x);
                split2(v.z, v.w, hv.y, lv.y);
                int kc = q >> 1;
                int off = m * 256 + ((kc ^ (m & 7)) * 16) + (q & 1) * 8;
                *reinterpret_cast<uint2*>(smem + A_HI + off) = hv;
                *reinterpret_cast<uint2*>(smem + A_LO + off) = lv;
            }
            cp_wait_all();  // B (first iter); no-op later
        } else {
            for (int c = tid; c < 64 * 16; c += 256) {
                int m = c >> 4, kc = c & 15;
                size_t gof = ((size_t)(row0 + m)) * 256 + kc * 16;
                int off = m * 256 + ((kc ^ (m & 7)) * 16);
                cp16(sb + A_HI + off, reinterpret_cast<const char*>(g_ahi) + gof);
                cp16(sb + A_LO + off, reinterpret_cast<const char*>(g_alo) + gof);
            }
            cp_wait_all();
        }
        __syncthreads();

        float acc[NT][4];
#pragma unroll
        for (int nt = 0; nt < NT; nt++)
#pragma unroll
            for (int j = 0; j < 4; j++) acc[nt][j] = 0.0f;

#pragma unroll
        for (int ks = 0; ks < 8; ks++) {
            uint32_t ah[4], al[4];
            {
                int r = wm + (lane & 15);
                int ch = ks * 2 + (lane >> 4);
                int off = r * 256 + ((ch ^ (r & 7)) * 16);
                ldsm_x4(ah, sb + A_HI + off);
                ldsm_x4(al, sb + A_LO + off);
            }
            uint32_t bh[NP][4], bl[NP][4];
#pragma unroll
            for (int p = 0; p < NP; p++) {
                int n = wn + p * 16 + (lane & 7) + ((lane >> 4) << 3);
                int ch = ks * 2 + ((lane >> 3) & 1);
                int off = n * 256 + ((ch ^ (n & 7)) * 16);
                ldsm_x4(bh[p], sb + B_HI + off);
                ldsm_x4(bl[p], sb + B_LO + off);
            }
#pragma unroll
            for (int nt = 0; nt < NT; nt++) {
                uint32_t h0 = bh[nt >> 1][(nt & 1) * 2], h1 = bh[nt >> 1][(nt & 1) * 2 + 1];
                uint32_t l0 = bl[nt >> 1][(nt & 1) * 2], l1 = bl[nt >> 1][(nt & 1) * 2 + 1];
                mma_bf16(acc[nt], ah, h0, h1);
                mma_bf16(acc[nt], ah, l0, l1);
                mma_bf16(acc[nt], al, h0, h1);
            }
        }

#pragma unroll
        for (int nt = 0; nt < NT; nt++) {
            int col = wn + nt * 8 + tig * 2;
            int m0 = row0 + wm + gid;
            if (m0 < N_NODES)
                *reinterpret_cast<float2*>(g_bufA + (size_t)m0 * NC + col) =
                    make_float2(acc[nt][0], acc[nt][1]);
            if (m0 + 8 < N_NODES)
                *reinterpret_cast<float2*>(g_bufA + (size_t)(m0 + 8) * NC + col) =
                    make_float2(acc[nt][2], acc[nt][3]);
        }
        __syncthreads();  // all warps done reading A before next tile overwrites
    }
}

// ---------------- CSR gather, shuffle-batched edges (packed int2 edge list) ----------------
__global__ void k_gather128_split(const float* __restrict__ b) {
    int node = (blockIdx.x * blockDim.x + threadIdx.x) >> 5;
    int lane = threadIdx.x & 31;
    if (node >= N_NODES) return;
    const float* t = g_bufA;
    float d = g_deg[node];
    float d2 = d * d;
    float4 self = *reinterpret_cast<const float4*>(t + (size_t)node * 128 + lane * 4);
    float4 bv = *reinterpret_cast<const float4*>(b + lane * 4);
    float4 acc;
    acc.x = fmaf(d2, self.x, bv.x);
    acc.y = fmaf(d2, self.y, bv.y);
    acc.z = fmaf(d2, self.z, bv.z);
    acc.w = fmaf(d2, self.w, bv.w);

    int s = g_rowptr[node], e = g_rowptr[node + 1];
    for (int base = s; base < e; base += 32) {
        int cnt = min(32, e - base);
        int rs = 0; float wn = 0.0f;
        if (base + lane < e) {
            int2 ep = g_epack[base + lane];
            rs = ep.x;
            wn = __int_as_float(ep.y);
        }
        int j = 0;
        for (; j + 4 <= cnt; j += 4) {
            int r0 = __shfl_sync(FULLMASK, rs, j + 0);
            int r1 = __shfl_sync(FULLMASK, rs, j + 1);
            int r2 = __shfl_sync(FULLMASK, rs, j + 2);
            int r3 = __shfl_sync(FULLMASK, rs, j + 3);
            float w0 = __shfl_sync(FULLMASK, wn, j + 0);
            float w1 = __shfl_sync(FULLMASK, wn, j + 1);
            float w2 = __shfl_sync(FULLMASK, wn, j + 2);
            float w3 = __shfl_sync(FULLMASK, wn, j + 3);
            float4 v0 = *reinterpret_cast<const float4*>(t + (size_t)r0 * 128 + lane * 4);
            float4 v1 = *reinterpret_cast<const float4*>(t + (size_t)r1 * 128 + lane * 4);
            float4 v2 = *reinterpret_cast<const float4*>(t + (size_t)r2 * 128 + lane * 4);
            float4 v3 = *reinterpret_cast<const float4*>(t + (size_t)r3 * 128 + lane * 4);
            acc.x = fmaf(w0, v0.x, acc.x); acc.y = fmaf(w0, v0.y, acc.y);
            acc.z = fmaf(w0, v0.z, acc.z); acc.w = fmaf(w0, v0.w, acc.w);
            acc.x = fmaf(w1, v1.x, acc.x); acc.y = fmaf(w1, v1.y, acc.y);
            acc.z = fmaf(w1, v1.z, acc.z); acc.w = fmaf(w1, v1.w, acc.w);
            acc.x = fmaf(w2, v2.x, acc.x); acc.y = fmaf(w2, v2.y, acc.y);
            acc.z = fmaf(w2, v2.z, acc.z); acc.w = fmaf(w2, v2.w, acc.w);
            acc.x = fmaf(w3, v3.x, acc.x); acc.y = fmaf(w3, v3.y, acc.y);
            acc.z = fmaf(w3, v3.z, acc.z); acc.w = fmaf(w3, v3.w, acc.w);
        }
        for (; j < cnt; j++) {
            int r0 = __shfl_sync(FULLMASK, rs, j);
            float w0 = __shfl_sync(FULLMASK, wn, j);
            float4 v0 = *reinterpret_cast<const float4*>(t + (size_t)r0 * 128 + lane * 4);
            acc.x = fmaf(w0, v0.x, acc.x); acc.y = fmaf(w0, v0.y, acc.y);
            acc.z = fmaf(w0, v0.z, acc.z); acc.w = fmaf(w0, v0.w, acc.w);
        }
    }
    acc.x = fmaxf(acc.x, 0.0f); acc.y = fmaxf(acc.y, 0.0f);
    acc.z = fmaxf(acc.z, 0.0f); acc.w = fmaxf(acc.w, 0.0f);
    uint2 hv, lv;
    split2(acc.x, acc.y, hv.x, lv.x);
    split2(acc.z, acc.w, hv.y, lv.y);
    reinterpret_cast<uint2*>(g_ahi)[node * 32 + lane] = hv;
    reinterpret_cast<uint2*>(g_alo)[node * 32 + lane] = lv;
}

// layer-3 gather; also restores the counts/cursor zero-invariant
__global__ void k_gather64(const float* __restrict__ b) {
    int gthread = blockIdx.x * blockDim.x + threadIdx.x;
    if (gthread < N_NODES) { g_counts[gthread] = 0; g_cursor[gthread] = 0; }
    int node = gthread >> 5;
    int lane = threadIdx.x & 31;
    if (node >= N_NODES) return;
    const float* t = g_bufA;
    float d = g_deg[node];
    float d2 = d * d;
    float2 self = *reinterpret_cast<const float2*>(t + (size_t)node * 64 + lane * 2);
    float2 bv = *reinterpret_cast<const float2*>(b + lane * 2);
    float2 acc;
    acc.x = fmaf(d2, self.x, bv.x);
    acc.y = fmaf(d2, self.y, bv.y);

    int s = g_rowptr[node], e = g_rowptr[node + 1];
    for (int base = s; base < e; base += 32) {
        int cnt = min(32, e - base);
        int rs = 0; float wn = 0.0f;
        if (base + lane < e) {
            int2 ep = g_epack[base + lane];
            rs = ep.x;
            wn = __int_as_float(ep.y);
        }
        int j = 0;
        for (; j + 4 <= cnt; j += 4) {
            int r0 = __shfl_sync(FULLMASK, rs, j + 0);
            int r1 = __shfl_sync(FULLMASK, rs, j + 1);
            int r2 = __shfl_sync(FULLMASK, rs, j + 2);
            int r3 = __shfl_sync(FULLMASK, rs, j + 3);
            float w0 = __shfl_sync(FULLMASK, wn, j + 0);
            float w1 = __shfl_sync(FULLMASK, wn, j + 1);
            float w2 = __shfl_sync(FULLMASK, wn, j + 2);
            float w3 = __shfl_sync(FULLMASK, wn, j + 3);
            float2 v0 = *reinterpret_cast<const float2*>(t + (size_t)r0 * 64 + lane * 2);
            float2 v1 = *reinterpret_cast<const float2*>(t + (size_t)r1 * 64 + lane * 2);
            float2 v2 = *reinterpret_cast<const float2*>(t + (size_t)r2 * 64 + lane * 2);
            float2 v3 = *reinterpret_cast<const float2*>(t + (size_t)r3 * 64 + lane * 2);
            acc.x = fmaf(w0, v0.x, acc.x); acc.y = fmaf(w0, v0.y, acc.y);
            acc.x = fmaf(w1, v1.x, acc.x); acc.y = fmaf(w1, v1.y, acc.y);
            acc.x = fmaf(w2, v2.x, acc.x); acc.y = fmaf(w2, v2.y, acc.y);
            acc.x = fmaf(w3, v3.x, acc.x); acc.y = fmaf(w3, v3.y, acc.y);
        }
        for (; j < cnt; j++) {
            int r0 = __shfl_sync(FULLMASK, rs, j);
            float w0 = __shfl_sync(FULLMASK, wn, j);
            float2 v0 = *reinterpret_cast<const float2*>(t + (size_t)r0 * 64 + lane * 2);
            acc.x = fmaf(w0, v0.x, acc.x); acc.y = fmaf(w0, v0.y, acc.y);
        }
    }
    *reinterpret_cast<float2*>(g_bufB + (size_t)node * 64 + lane * 2) = acc;
}

// ---------------- mean pool + FC (last-block) ----------------
__global__ void k_pool_fc(const void* __restrict__ batch,
                          const float* __restrict__ Wf1, const float* __restrict__ bf1,
                          const float* __restrict__ Wf2, const float* __restrict__ bf2,
                          float* __restrict__ out) {
    int g = blockIdx.x;
    const int N = N_NODES;
    int is64 = g_is64;
    int lo = 0, hi = N;
    while (lo < hi) { int mid = (lo + hi) >> 1; if (load_idx2(batch, mid, is64) < g) lo = mid + 1; else hi = mid; }
    int start = lo;
    lo = start; hi = N;
    while (lo < hi) { int mid = (lo + hi) >> 1; if (load_idx2(batch, mid, is64) < g + 1) lo = mid + 1; else hi = mid; }
    int end = lo;

    int f = threadIdx.x & 63;
    int grp = threadIdx.x >> 6;
    __shared__ float red[4][64];

    float acc = 0.0f;
    for (int i = start + grp; i < end; i += 4)
        acc += fmaxf(g_bufB[(size_t)i * 64 + f], 0.0f);
    red[grp][f] = acc;
    __syncthreads();
    if (grp == 0) {
        float s = red[0][f] + red[1][f] + red[2][f] + red[3][f];
        float cnt = (float)(end - start);
        g_pooled[g * 64 + f] = s / fmaxf(cnt, 1.0f);
    }

    __threadfence();
    __shared__ int amLast;
    if (threadIdx.x == 0)
        amLast = (atomicAdd(&g_pool_done, 1) == (int)gridDim.x - 1);
    __syncthreads();
    if (!amLast) return;

    __shared__ float P[64 * 64];
    __shared__ float Hd[64 * 32];
    for (int i = threadIdx.x; i < 64 * 64; i += 256) P[i] = g_pooled[i];
    __syncthreads();
    for (int e2 = threadIdx.x; e2 < 64 * 32; e2 += 256) {
        int gi = e2 >> 5, j = e2 & 31;
        float s = bf1[j];
#pragma unroll
        for (int k = 0; k < 64; k++) s += P[gi * 64 + k] * Wf1[k * 32 + j];
        Hd[e2] = fmaxf(s, 0.0f);
    }
    __syncthreads();
    for (int e2 = threadIdx.x; e2 < 64 * 10; e2 += 256) {
        int gi = e2 / 10, j = e2 % 10;
        float s = bf2[j];
#pragma unroll
        for (int k = 0; k < 32; k++) s += Hd[gi * 32 + k] * Wf2[k * 10 + j];
        out[e2] = s;
    }
    if (threadIdx.x == 0) g_pool_done = 0;
}

// ---------------- launch ----------------
extern "C" void kernel_launch(void* const* d_in, const int* in_sizes, int n_in,
                              void* d_out, int out_size) {
    const float *x = 0, *W1 = 0, *b1 = 0, *W2 = 0, *b2 = 0, *W3 = 0, *b3 = 0;
    const float *Wf1 = 0, *bf1 = 0, *Wf2 = 0, *bf2 = 0;
    const void *ei = 0, *batch = 0;
    for (int i = 0; i < n_in; i++) {
        const void* p = d_in[i];
        switch (in_sizes[i]) {
            case 6400000: x = (const float*)p; break;
            case 1200000: ei = p; break;
            case 50000:   batch = p; break;
            case 16384:   if (!W1) W1 = (const float*)p; else W2 = (const float*)p; break;
            case 128:     if (!b1) b1 = (const float*)p; else b2 = (const float*)p; break;
            case 8192:    W3 = (const float*)p; break;
            case 64:      b3 = (const float*)p; break;
            case 2048:    Wf1 = (const float*)p; break;
            case 32:      bf1 = (const float*)p; break;
            case 320:     Wf2 = (const float*)p; break;
            case 10:      bf2 = (const float*)p; break;
        }
    }

    const int N = N_NODES;
    const int SMEM128 = 32768 + 2 * 128 * 256;  // 98304
    const int SMEM64  = 32768 + 2 * 64 * 256;   // 65536
    cudaFuncSetAttribute(k_gemm_mma<128, true>,  cudaFuncAttributeMaxDynamicSharedMemorySize, SMEM128);
    cudaFuncSetAttribute(k_gemm_mma<128, false>, cudaFuncAttributeMaxDynamicSharedMemorySize, SMEM128);
    cudaFuncSetAttribute(k_gemm_mma<64, false>,  cudaFuncAttributeMaxDynamicSharedMemorySize, SMEM64);

    // ---- fused CSR build (counts/cursor are zero by invariant), single stream ----
    k_csr<<<CSR_BLOCKS, 256>>>(ei, W1, W2, W3);

    int gath_grid = (N * 32 + 255) / 256;

    // layer 1
    k_gemm_mma<128, true><<<GEMM_BLOCKS, 256, SMEM128>>>(x, 0);
    k_gather128_split<<<gath_grid, 256>>>(b1);
    // layer 2
    k_gemm_mma<128, false><<<GEMM_BLOCKS, 256, SMEM128>>>(nullptr, 16384);
    k_gather128_split<<<gath_grid, 256>>>(b2);
    // layer 3
    k_gemm_mma<64, false><<<GEMM_BLOCKS, 256, SMEM64>>>(nullptr, 32768);
    k_gather64<<<gath_grid, 256>>>(b3);

    // pool + FC fused
    k_pool_fc<<<N_GRAPHS, 256>>>(batch, Wf1, bf1, Wf2, bf2, (float*)d_out);
}